// round 3
// baseline (speedup 1.0000x reference)
#include <cuda_runtime.h>
#include <cuda_bf16.h>

// Shapes (fixed by the problem)
#define BB   2
#define HQ   32
#define HK   8
#define SS   8192
#define DD   128
#define HID  128
#define BSZ  16
#define NB   512
#define NTILE 16   // n-rows per projection block

// Scratch (allocation-free rule: __device__ globals)
__device__ float g_qh[BB * HQ * NB * HID];   // 16.8 MB
__device__ float g_kh[BB * HK * NB * HID];   //  4.2 MB

// ---------------------------------------------------------------------------
// Kernel 1: pool_cat + projection + RoPE, fused.
// One block handles NTILE consecutive n-blocks of one (b,h): loads w column
// once per cc and reuses it across 16 rows (kills the L2 w-traffic blowup).
// ---------------------------------------------------------------------------
template <int NH, bool IS_Q>
__global__ __launch_bounds__(128, 4)
void proj_kernel(const float* __restrict__ x,
                 const float* __restrict__ w,
                 const float* __restrict__ cosb,
                 const float* __restrict__ sinb)
{
    __shared__ float cs[2 * DD][20];      // [cc][n_local], padded (20 KB)
    __shared__ float os[NTILE][DD + 4];   // rope staging (8.4 KB)

    const int bid = blockIdx.x;
    const int nt  = bid % (NB / NTILE);
    const int h   = (bid / (NB / NTILE)) % NH;
    const int b   = bid / ((NB / NTILE) * NH);
    const int n0  = nt * NTILE;
    const int t   = threadIdx.x;          // 0..127 == d

    // ---- pooling: mean & max over BSZ=16 rows per n ----
    #pragma unroll
    for (int nl = 0; nl < NTILE; nl++) {
        const float* xp = x + (((size_t)(b * NH + h)) * SS + (size_t)(n0 + nl) * BSZ) * DD + t;
        float s = 0.f, mx = -3.0e38f;
        #pragma unroll
        for (int i = 0; i < BSZ; i++) {
            float v = xp[i * DD];
            s += v;
            mx = fmaxf(mx, v);
        }
        cs[t][nl]      = s * (1.0f / BSZ);
        cs[DD + t][nl] = mx;
    }
    __syncthreads();

    // ---- GEMV x16: acc[nl] = sum_cc c[nl][cc] * w[h][cc][t] ----
    float acc[NTILE];
    #pragma unroll
    for (int nl = 0; nl < NTILE; nl++) acc[nl] = 0.f;

    const float* wp = w + ((size_t)h * (2 * DD)) * HID + t;
    #pragma unroll 4
    for (int cc = 0; cc < 2 * DD; cc++) {
        float wv = __ldg(&wp[(size_t)cc * HID]);
        const float4* cp = (const float4*)&cs[cc][0];
        float4 c0 = cp[0], c1 = cp[1], c2 = cp[2], c3 = cp[3];
        acc[0]  += c0.x * wv;  acc[1]  += c0.y * wv;
        acc[2]  += c0.z * wv;  acc[3]  += c0.w * wv;
        acc[4]  += c1.x * wv;  acc[5]  += c1.y * wv;
        acc[6]  += c1.z * wv;  acc[7]  += c1.w * wv;
        acc[8]  += c2.x * wv;  acc[9]  += c2.y * wv;
        acc[10] += c2.z * wv;  acc[11] += c2.w * wv;
        acc[12] += c3.x * wv;  acc[13] += c3.y * wv;
        acc[14] += c3.z * wv;  acc[15] += c3.w * wv;
    }

    #pragma unroll
    for (int nl = 0; nl < NTILE; nl++) os[nl][t] = acc[nl];
    __syncthreads();

    // ---- RoPE + store ----
    float* dst = IS_Q ? g_qh : g_kh;
    #pragma unroll
    for (int nl = 0; nl < NTILE; nl++) {
        const int n = n0 + nl;
        const float cv = cosb[((size_t)b * NB + n) * HID + t];
        const float sv = sinb[((size_t)b * NB + n) * HID + t];
        const float v0 = os[nl][t];
        const float vr = (t < HID / 2) ? -os[nl][t + HID / 2] : os[nl][t - HID / 2];
        dst[(((size_t)(b * NH + h)) * NB + n) * HID + t] = v0 * cv + vr * sv;
    }
}

// ---------------------------------------------------------------------------
// Kernel 2: block-causal logits.  C[m, j] = qh[m,:] . kh[j,:] / sqrt(HID)
// 64x64 tiles, skip tiles entirely above the causal diagonal.
// ---------------------------------------------------------------------------
__global__ __launch_bounds__(256, 2)
void logits_kernel(float* __restrict__ out)
{
    const int b  = blockIdx.z;
    const int h  = blockIdx.y;
    const int mt = blockIdx.x;
    const int m0 = mt * 64;

    const float* A  = g_qh + (((size_t)(b * HQ + h)) * NB + m0) * HID;
    const float* Bk = g_kh + (((size_t)(b * HK + h / (HQ / HK))) * NB) * HID;

    __shared__ float As[64][68];   // [k-in-chunk][m], padded
    __shared__ float Bs[64][68];   // [k-in-chunk][n]

    const int tid  = threadIdx.x;
    const int ty   = tid / 16;     // row group
    const int tx   = tid % 16;     // col group
    const int lrow = tid / 16;     // 0..15 (loader row)
    const int lk4  = tid % 16;     // 0..15 (loader k-float4)
    const float scale = 0.08838834764831845f;   // 1/sqrt(128)

    for (int j0 = 0; j0 <= m0; j0 += 64) {
        float acc[16];
        #pragma unroll
        for (int i = 0; i < 16; i++) acc[i] = 0.f;

        #pragma unroll
        for (int kc = 0; kc < HID; kc += 64) {
            __syncthreads();
            #pragma unroll
            for (int r = 0; r < 4; r++) {
                const int rr = lrow + r * 16;
                float4 va = *(const float4*)&A[(size_t)rr * HID + kc + lk4 * 4];
                As[lk4 * 4 + 0][rr] = va.x;
                As[lk4 * 4 + 1][rr] = va.y;
                As[lk4 * 4 + 2][rr] = va.z;
                As[lk4 * 4 + 3][rr] = va.w;
                float4 vb = *(const float4*)&Bk[((size_t)(j0 + rr)) * HID + kc + lk4 * 4];
                Bs[lk4 * 4 + 0][rr] = vb.x;
                Bs[lk4 * 4 + 1][rr] = vb.y;
                Bs[lk4 * 4 + 2][rr] = vb.z;
                Bs[lk4 * 4 + 3][rr] = vb.w;
            }
            __syncthreads();

            #pragma unroll 8
            for (int k = 0; k < 64; k++) {
                float4 a4 = *(const float4*)&As[k][ty * 4];
                float4 b4 = *(const float4*)&Bs[k][tx * 4];
                acc[0]  += a4.x * b4.x;  acc[1]  += a4.x * b4.y;
                acc[2]  += a4.x * b4.z;  acc[3]  += a4.x * b4.w;
                acc[4]  += a4.y * b4.x;  acc[5]  += a4.y * b4.y;
                acc[6]  += a4.y * b4.z;  acc[7]  += a4.y * b4.w;
                acc[8]  += a4.z * b4.x;  acc[9]  += a4.z * b4.y;
                acc[10] += a4.z * b4.z;  acc[11] += a4.z * b4.w;
                acc[12] += a4.w * b4.x;  acc[13] += a4.w * b4.y;
                acc[14] += a4.w * b4.z;  acc[15] += a4.w * b4.w;
            }
        }

        #pragma unroll
        for (int i = 0; i < 4; i++) {
            const int row = ty * 4 + i;
            float4 o;
            o.x = acc[i * 4 + 0] * scale;
            o.y = acc[i * 4 + 1] * scale;
            o.z = acc[i * 4 + 2] * scale;
            o.w = acc[i * 4 + 3] * scale;
            *(float4*)&out[(((size_t)(b * HQ + h)) * NB + (m0 + row)) * NB + j0 + tx * 4] = o;
        }
    }
}

// ---------------------------------------------------------------------------
// Kernel 3: in-place masked softmax per row (masked cols -> exact 0, matching
// fp32 exp(-1e9 - max) underflow in the reference).
// ---------------------------------------------------------------------------
__global__ __launch_bounds__(128)
void softmax_kernel(float* __restrict__ out)
{
    const int row = blockIdx.x;            // ((b*HQ+h)*NB + i)
    const int i   = row & (NB - 1);
    float* p = out + (size_t)row * NB;
    const int t = threadIdx.x;             // 128

    float v[4];
    float mx = -3.0e38f;
    #pragma unroll
    for (int jj = 0; jj < 4; jj++) {
        const int j = t + jj * 128;
        v[jj] = (j <= i) ? p[j] : -3.0e38f;
        mx = fmaxf(mx, v[jj]);
    }
    #pragma unroll
    for (int o = 16; o; o >>= 1) mx = fmaxf(mx, __shfl_xor_sync(0xffffffffu, mx, o));

    __shared__ float red[4];
    if ((t & 31) == 0) red[t >> 5] = mx;
    __syncthreads();
    mx = fmaxf(fmaxf(red[0], red[1]), fmaxf(red[2], red[3]));
    __syncthreads();

    float s = 0.f;
    #pragma unroll
    for (int jj = 0; jj < 4; jj++) {
        const int j = t + jj * 128;
        v[jj] = (j <= i) ? expf(v[jj] - mx) : 0.f;
        s += v[jj];
    }
    #pragma unroll
    for (int o = 16; o; o >>= 1) s += __shfl_xor_sync(0xffffffffu, s, o);
    if ((t & 31) == 0) red[t >> 5] = s;
    __syncthreads();
    s = red[0] + red[1] + red[2] + red[3];

    const float inv = 1.0f / s;
    #pragma unroll
    for (int jj = 0; jj < 4; jj++) {
        const int j = t + jj * 128;
        p[j] = v[jj] * inv;
    }
}

// ---------------------------------------------------------------------------
extern "C" void kernel_launch(void* const* d_in, const int* in_sizes, int n_in,
                              void* d_out, int out_size)
{
    const float* q    = (const float*)d_in[0];
    const float* k    = (const float*)d_in[1];
    // d_in[2] = attention_mask (block-causal tril, reconstructed analytically)
    const float* cosb = (const float*)d_in[3];
    const float* sinb = (const float*)d_in[4];
    const float* wq   = (const float*)d_in[5];
    const float* wk   = (const float*)d_in[6];
    float* out = (float*)d_out;

    // 1) pool + project + rope
    proj_kernel<HQ, true ><<<BB * HQ * (NB / NTILE), 128>>>(q, wq, cosb, sinb);
    proj_kernel<HK, false><<<BB * HK * (NB / NTILE), 128>>>(k, wk, cosb, sinb);

    // 2) causal logits
    dim3 lg(NB / 64, HQ, BB);
    logits_kernel<<<lg, 256>>>(out);

    // 3) masked softmax in place
    softmax_kernel<<<BB * HQ * NB, 128>>>(out);
}

// round 4
// speedup vs baseline: 1.1999x; 1.1999x over previous
#include <cuda_runtime.h>
#include <cuda_bf16.h>

// Shapes (fixed by the problem)
#define BB   2
#define HQ   32
#define HK   8
#define SS   8192
#define DD   128
#define HID  128
#define BSZ  16
#define NB   512
#define NTILE 16   // n-rows per projection block

// Scratch (allocation-free rule: __device__ globals)
__device__ float g_qh[BB * HQ * NB * HID];   // 16.8 MB
__device__ float g_kh[BB * HK * NB * HID];   //  4.2 MB

// ---- packed fp32x2 helpers (sm_10x packed-FFMA path; ptxas won't auto-fuse) ----
__device__ __forceinline__ unsigned long long pack2(float lo, float hi) {
    unsigned long long r;
    asm("mov.b64 %0, {%1, %2};" : "=l"(r) : "f"(lo), "f"(hi));
    return r;
}
__device__ __forceinline__ void fma2(unsigned long long& d,
                                     unsigned long long a,
                                     unsigned long long b) {
    asm("fma.rn.f32x2 %0, %1, %2, %0;" : "+l"(d) : "l"(a), "l"(b));
}
__device__ __forceinline__ float2 unpack2(unsigned long long v) {
    float2 f;
    asm("mov.b64 {%0, %1}, %2;" : "=f"(f.x), "=f"(f.y) : "l"(v));
    return f;
}

// ---------------------------------------------------------------------------
// Kernel 1: pool_cat + projection + RoPE, fused.
// One block handles NTILE consecutive n-blocks of one (b,h). GEMV inner loop
// runs on the packed f32x2 pipe (8 FFMA2 replace 16 FFMA per cc).
// ---------------------------------------------------------------------------
template <int NH, bool IS_Q>
__global__ __launch_bounds__(128, 4)
void proj_kernel(const float* __restrict__ x,
                 const float* __restrict__ w,
                 const float* __restrict__ cosb,
                 const float* __restrict__ sinb)
{
    __shared__ float cs[2 * DD][20];      // [cc][n_local], 16B-aligned rows (80B)
    __shared__ float os[NTILE][DD + 4];   // rope staging

    const int bid = blockIdx.x;
    const int nt  = bid % (NB / NTILE);
    const int h   = (bid / (NB / NTILE)) % NH;
    const int b   = bid / ((NB / NTILE) * NH);
    const int n0  = nt * NTILE;
    const int t   = threadIdx.x;          // 0..127 == d

    // ---- pooling: mean & max over BSZ=16 rows per n ----
    #pragma unroll
    for (int nl = 0; nl < NTILE; nl++) {
        const float* xp = x + (((size_t)(b * NH + h)) * SS + (size_t)(n0 + nl) * BSZ) * DD + t;
        float s = 0.f, mx = -3.0e38f;
        #pragma unroll
        for (int i = 0; i < BSZ; i++) {
            float v = xp[i * DD];
            s += v;
            mx = fmaxf(mx, v);
        }
        cs[t][nl]      = s * (1.0f / BSZ);
        cs[DD + t][nl] = mx;
    }
    __syncthreads();

    // ---- GEMV x16 on packed f32x2: acc pairs over nl ----
    unsigned long long acc[8];
    #pragma unroll
    for (int p = 0; p < 8; p++) acc[p] = 0ull;

    const float* wp = w + ((size_t)h * (2 * DD)) * HID + t;
    #pragma unroll 4
    for (int cc = 0; cc < 2 * DD; cc++) {
        float wv = __ldg(&wp[(size_t)cc * HID]);
        unsigned long long wv2 = pack2(wv, wv);
        const ulonglong2* cp = (const ulonglong2*)&cs[cc][0];
        ulonglong2 c0 = cp[0], c1 = cp[1], c2 = cp[2], c3 = cp[3];
        fma2(acc[0], wv2, c0.x);  fma2(acc[1], wv2, c0.y);
        fma2(acc[2], wv2, c1.x);  fma2(acc[3], wv2, c1.y);
        fma2(acc[4], wv2, c2.x);  fma2(acc[5], wv2, c2.y);
        fma2(acc[6], wv2, c3.x);  fma2(acc[7], wv2, c3.y);
    }

    #pragma unroll
    for (int p = 0; p < 8; p++) {
        float2 f = unpack2(acc[p]);
        os[2 * p + 0][t] = f.x;
        os[2 * p + 1][t] = f.y;
    }
    __syncthreads();

    // ---- RoPE + store ----
    float* dst = IS_Q ? g_qh : g_kh;
    #pragma unroll
    for (int nl = 0; nl < NTILE; nl++) {
        const int n = n0 + nl;
        const float cv = cosb[((size_t)b * NB + n) * HID + t];
        const float sv = sinb[((size_t)b * NB + n) * HID + t];
        const float v0 = os[nl][t];
        const float vr = (t < HID / 2) ? -os[nl][t + HID / 2] : os[nl][t - HID / 2];
        dst[(((size_t)(b * NH + h)) * NB + n) * HID + t] = v0 * cv + vr * sv;
    }
}

// ---------------------------------------------------------------------------
// Kernel 2: block-causal logits.  C[m, j] = qh[m,:] . kh[j,:] / sqrt(HID)
// One 64x64 causal tile per block (flattened triangular grid -> uniform work).
// Inner loop on packed f32x2 (8 FFMA2 per k instead of 16 FFMA).
// ---------------------------------------------------------------------------
__global__ __launch_bounds__(256)
void logits_kernel(float* __restrict__ out)
{
    const int b  = blockIdx.z;
    const int h  = blockIdx.y;
    const int ti = blockIdx.x;            // 0..35 triangular tile index

    // decode triangular index: ti = mt*(mt+1)/2 + jt, jt <= mt
    int mt = (int)((sqrtf(8.0f * ti + 1.0f) - 1.0f) * 0.5f);
    while ((mt + 1) * (mt + 2) / 2 <= ti) mt++;
    while (mt * (mt + 1) / 2 > ti) mt--;
    const int jt = ti - mt * (mt + 1) / 2;
    const int m0 = mt * 64;
    const int j0 = jt * 64;

    const float* A  = g_qh + (((size_t)(b * HQ + h)) * NB + m0) * HID;
    const float* Bk = g_kh + (((size_t)(b * HK + h / (HQ / HK))) * NB + j0) * HID;

    __shared__ float As[64][68];   // [k-in-chunk][m], rows 272B (16B multiple)
    __shared__ float Bs[64][68];   // [k-in-chunk][n]

    const int tid  = threadIdx.x;
    const int ty   = tid / 16;     // row group (0..15)
    const int tx   = tid % 16;     // col group (0..15)
    const float scale = 0.08838834764831845f;   // 1/sqrt(128)

    unsigned long long acc[8];     // acc[i*2+p]: row ty*4+i, cols tx*4+2p..+1
    #pragma unroll
    for (int i = 0; i < 8; i++) acc[i] = 0ull;

    #pragma unroll
    for (int kc = 0; kc < HID; kc += 64) {
        __syncthreads();
        #pragma unroll
        for (int r = 0; r < 4; r++) {
            const int rr = ty + r * 16;
            float4 va = *(const float4*)&A[(size_t)rr * HID + kc + tx * 4];
            As[tx * 4 + 0][rr] = va.x;
            As[tx * 4 + 1][rr] = va.y;
            As[tx * 4 + 2][rr] = va.z;
            As[tx * 4 + 3][rr] = va.w;
            float4 vb = *(const float4*)&Bk[(size_t)rr * HID + kc + tx * 4];
            Bs[tx * 4 + 0][rr] = vb.x;
            Bs[tx * 4 + 1][rr] = vb.y;
            Bs[tx * 4 + 2][rr] = vb.z;
            Bs[tx * 4 + 3][rr] = vb.w;
        }
        __syncthreads();

        #pragma unroll 8
        for (int k = 0; k < 64; k++) {
            float4 a4 = *(const float4*)&As[k][ty * 4];
            ulonglong2 bq = *(const ulonglong2*)&Bs[k][tx * 4];
            unsigned long long ax = pack2(a4.x, a4.x);
            unsigned long long ay = pack2(a4.y, a4.y);
            unsigned long long az = pack2(a4.z, a4.z);
            unsigned long long aw = pack2(a4.w, a4.w);
            fma2(acc[0], ax, bq.x);  fma2(acc[1], ax, bq.y);
            fma2(acc[2], ay, bq.x);  fma2(acc[3], ay, bq.y);
            fma2(acc[4], az, bq.x);  fma2(acc[5], az, bq.y);
            fma2(acc[6], aw, bq.x);  fma2(acc[7], aw, bq.y);
        }
    }

    #pragma unroll
    for (int i = 0; i < 4; i++) {
        const int row = ty * 4 + i;
        float2 f0 = unpack2(acc[i * 2 + 0]);
        float2 f1 = unpack2(acc[i * 2 + 1]);
        float4 o;
        o.x = f0.x * scale;
        o.y = f0.y * scale;
        o.z = f1.x * scale;
        o.w = f1.y * scale;
        *(float4*)&out[(((size_t)(b * HQ + h)) * NB + (m0 + row)) * NB + j0 + tx * 4] = o;
    }
}

// ---------------------------------------------------------------------------
// Kernel 3: in-place masked softmax per row (masked cols -> exact 0, matching
// fp32 exp(-1e9 - max) underflow in the reference).
// ---------------------------------------------------------------------------
__global__ __launch_bounds__(128)
void softmax_kernel(float* __restrict__ out)
{
    const int row = blockIdx.x;            // ((b*HQ+h)*NB + i)
    const int i   = row & (NB - 1);
    float* p = out + (size_t)row * NB;
    const int t = threadIdx.x;             // 128

    float v[4];
    float mx = -3.0e38f;
    #pragma unroll
    for (int jj = 0; jj < 4; jj++) {
        const int j = t + jj * 128;
        v[jj] = (j <= i) ? p[j] : -3.0e38f;
        mx = fmaxf(mx, v[jj]);
    }
    #pragma unroll
    for (int o = 16; o; o >>= 1) mx = fmaxf(mx, __shfl_xor_sync(0xffffffffu, mx, o));

    __shared__ float red[4];
    if ((t & 31) == 0) red[t >> 5] = mx;
    __syncthreads();
    mx = fmaxf(fmaxf(red[0], red[1]), fmaxf(red[2], red[3]));
    __syncthreads();

    float s = 0.f;
    #pragma unroll
    for (int jj = 0; jj < 4; jj++) {
        const int j = t + jj * 128;
        v[jj] = (j <= i) ? expf(v[jj] - mx) : 0.f;
        s += v[jj];
    }
    #pragma unroll
    for (int o = 16; o; o >>= 1) s += __shfl_xor_sync(0xffffffffu, s, o);
    if ((t & 31) == 0) red[t >> 5] = s;
    __syncthreads();
    s = red[0] + red[1] + red[2] + red[3];

    const float inv = 1.0f / s;
    #pragma unroll
    for (int jj = 0; jj < 4; jj++) {
        const int j = t + jj * 128;
        p[j] = v[jj] * inv;
    }
}

// ---------------------------------------------------------------------------
extern "C" void kernel_launch(void* const* d_in, const int* in_sizes, int n_in,
                              void* d_out, int out_size)
{
    const float* q    = (const float*)d_in[0];
    const float* k    = (const float*)d_in[1];
    // d_in[2] = attention_mask (block-causal tril, reconstructed analytically)
    const float* cosb = (const float*)d_in[3];
    const float* sinb = (const float*)d_in[4];
    const float* wq   = (const float*)d_in[5];
    const float* wk   = (const float*)d_in[6];
    float* out = (float*)d_out;

    // 1) pool + project + rope
    proj_kernel<HQ, true ><<<BB * HQ * (NB / NTILE), 128>>>(q, wq, cosb, sinb);
    proj_kernel<HK, false><<<BB * HK * (NB / NTILE), 128>>>(k, wk, cosb, sinb);

    // 2) causal logits (one uniform 64x64 tile per block, triangular grid)
    dim3 lg(36, HQ, BB);
    logits_kernel<<<lg, 256>>>(out);

    // 3) masked softmax in place
    softmax_kernel<<<BB * HQ * NB, 128>>>(out);
}

// round 8
// speedup vs baseline: 1.3807x; 1.1507x over previous
#include <cuda_runtime.h>
#include <cuda_bf16.h>
#include <cstdint>

// Shapes (fixed by the problem)
#define BB   2
#define HQ   32
#define HK   8
#define SS   8192
#define DD   128
#define HID  128
#define BSZ  16
#define NB   512
#define NTILE 16   // n-rows per projection block

// Scratch (allocation-free rule: __device__ globals)
__device__ float g_qh[BB * HQ * NB * HID];   // 16.8 MB
__device__ float g_kh[BB * HK * NB * HID];   //  4.2 MB

// ---- packed fp32x2 helpers (proj kernel) ----
__device__ __forceinline__ unsigned long long pack2(float lo, float hi) {
    unsigned long long r;
    asm("mov.b64 %0, {%1, %2};" : "=l"(r) : "f"(lo), "f"(hi));
    return r;
}
__device__ __forceinline__ void fma2(unsigned long long& d,
                                     unsigned long long a,
                                     unsigned long long b) {
    asm("fma.rn.f32x2 %0, %1, %2, %0;" : "+l"(d) : "l"(a), "l"(b));
}
__device__ __forceinline__ float2 unpack2(unsigned long long v) {
    float2 f;
    asm("mov.b64 {%0, %1}, %2;" : "=f"(f.x), "=f"(f.y) : "l"(v));
    return f;
}

// ---------------------------------------------------------------------------
// Kernel 1: pool_cat + projection + RoPE, fused. (unchanged from R4)
// ---------------------------------------------------------------------------
template <int NH, bool IS_Q>
__global__ __launch_bounds__(128, 4)
void proj_kernel(const float* __restrict__ x,
                 const float* __restrict__ w,
                 const float* __restrict__ cosb,
                 const float* __restrict__ sinb)
{
    __shared__ float cs[2 * DD][20];
    __shared__ float os[NTILE][DD + 4];

    const int bid = blockIdx.x;
    const int nt  = bid % (NB / NTILE);
    const int h   = (bid / (NB / NTILE)) % NH;
    const int b   = bid / ((NB / NTILE) * NH);
    const int n0  = nt * NTILE;
    const int t   = threadIdx.x;

    #pragma unroll
    for (int nl = 0; nl < NTILE; nl++) {
        const float* xp = x + (((size_t)(b * NH + h)) * SS + (size_t)(n0 + nl) * BSZ) * DD + t;
        float s = 0.f, mx = -3.0e38f;
        #pragma unroll
        for (int i = 0; i < BSZ; i++) {
            float v = xp[i * DD];
            s += v;
            mx = fmaxf(mx, v);
        }
        cs[t][nl]      = s * (1.0f / BSZ);
        cs[DD + t][nl] = mx;
    }
    __syncthreads();

    unsigned long long acc[8];
    #pragma unroll
    for (int p = 0; p < 8; p++) acc[p] = 0ull;

    const float* wp = w + ((size_t)h * (2 * DD)) * HID + t;
    #pragma unroll 4
    for (int cc = 0; cc < 2 * DD; cc++) {
        float wv = __ldg(&wp[(size_t)cc * HID]);
        unsigned long long wv2 = pack2(wv, wv);
        const ulonglong2* cp = (const ulonglong2*)&cs[cc][0];
        ulonglong2 c0 = cp[0], c1 = cp[1], c2 = cp[2], c3 = cp[3];
        fma2(acc[0], wv2, c0.x);  fma2(acc[1], wv2, c0.y);
        fma2(acc[2], wv2, c1.x);  fma2(acc[3], wv2, c1.y);
        fma2(acc[4], wv2, c2.x);  fma2(acc[5], wv2, c2.y);
        fma2(acc[6], wv2, c3.x);  fma2(acc[7], wv2, c3.y);
    }

    #pragma unroll
    for (int p = 0; p < 8; p++) {
        float2 f = unpack2(acc[p]);
        os[2 * p + 0][t] = f.x;
        os[2 * p + 1][t] = f.y;
    }
    __syncthreads();

    float* dst = IS_Q ? g_qh : g_kh;
    #pragma unroll
    for (int nl = 0; nl < NTILE; nl++) {
        const int n = n0 + nl;
        const float cv = cosb[((size_t)b * NB + n) * HID + t];
        const float sv = sinb[((size_t)b * NB + n) * HID + t];
        const float v0 = os[nl][t];
        const float vr = (t < HID / 2) ? -os[nl][t + HID / 2] : os[nl][t - HID / 2];
        dst[(((size_t)(b * NH + h)) * NB + n) * HID + t] = v0 * cv + vr * sv;
    }
}

// ---------------------------------------------------------------------------
// Kernel 2: block-causal logits via mma.sync m16n8k16 bf16, 2-term split
// (hi + lo), 3 MMA passes: AhBh + AhBl + AlBh.  D = A @ B^T, fp32 accum.
// One CTA = 128x128 tile; 8 warps in 2x4 grid; warp tile 64x32.
// ---------------------------------------------------------------------------
__device__ __forceinline__ void mma_bf16(float* c, const uint32_t* a, const uint32_t* b) {
    asm volatile(
        "mma.sync.aligned.m16n8k16.row.col.f32.bf16.bf16.f32 "
        "{%0,%1,%2,%3}, {%4,%5,%6,%7}, {%8,%9}, {%0,%1,%2,%3};\n"
        : "+f"(c[0]), "+f"(c[1]), "+f"(c[2]), "+f"(c[3])
        : "r"(a[0]), "r"(a[1]), "r"(a[2]), "r"(a[3]), "r"(b[0]), "r"(b[1]));
}

__device__ __forceinline__ void split_pair(float x, float y, uint32_t& hi, uint32_t& lo) {
    __nv_bfloat16 hx = __float2bfloat16(x);
    __nv_bfloat16 hy = __float2bfloat16(y);
    float lx = x - __bfloat162float(hx);
    float ly = y - __bfloat162float(hy);
    __nv_bfloat162 h2 = __halves2bfloat162(hx, hy);          // low half = x-elem
    __nv_bfloat162 l2 = __floats2bfloat162_rn(lx, ly);
    hi = *(uint32_t*)&h2;
    lo = *(uint32_t*)&l2;
}

#define LSTR 20   // uint32 (bf16-pair) stride per row: conflict-free fragments

__global__ __launch_bounds__(256, 1)
void logits_mma_kernel(float* __restrict__ out)
{
    __shared__ uint32_t sAh[128 * LSTR], sAl[128 * LSTR];
    __shared__ uint32_t sBh[128 * LSTR], sBl[128 * LSTR];

    const int b  = blockIdx.z;
    const int h  = blockIdx.y;
    const int ti = blockIdx.x;                 // 0..9 triangular over 4 row-tiles
    const int mt4 = (ti >= 6) ? 3 : (ti >= 3) ? 2 : (ti >= 1) ? 1 : 0;
    const int jt  = ti - mt4 * (mt4 + 1) / 2;
    const int m0  = mt4 * 128;
    const int j0  = jt * 128;

    const float* Ag = g_qh + (((size_t)(b * HQ + h)) * NB + m0) * HID;
    const float* Bg = g_kh + (((size_t)(b * HK + h / (HQ / HK))) * NB + j0) * HID;

    const int tid  = threadIdx.x;
    const int lane = tid & 31, wid = tid >> 5;
    const int wm = wid >> 2, wn = wid & 3;     // warp grid 2 x 4
    const int g  = lane >> 2, tg = lane & 3;   // fragment coords

    float acc[4][4][4];
    #pragma unroll
    for (int i = 0; i < 4; i++)
        #pragma unroll
        for (int j = 0; j < 4; j++)
            #pragma unroll
            for (int r = 0; r < 4; r++) acc[i][j][r] = 0.f;

    const int lr0 = tid >> 3;       // 0..31
    const int lq  = tid & 7;        // float4 index within 32-k chunk

    for (int kc = 0; kc < 4; kc++) {            // 4 chunks of 32 k
        __syncthreads();
        #pragma unroll
        for (int pass = 0; pass < 4; pass++) {
            const int r = pass * 32 + lr0;
            float4 va = *(const float4*)&Ag[(size_t)r * HID + kc * 32 + lq * 4];
            uint32_t h0, l0, h1, l1;
            split_pair(va.x, va.y, h0, l0);
            split_pair(va.z, va.w, h1, l1);
            sAh[r * LSTR + lq * 2 + 0] = h0;  sAh[r * LSTR + lq * 2 + 1] = h1;
            sAl[r * LSTR + lq * 2 + 0] = l0;  sAl[r * LSTR + lq * 2 + 1] = l1;

            float4 vb = *(const float4*)&Bg[(size_t)r * HID + kc * 32 + lq * 4];
            split_pair(vb.x, vb.y, h0, l0);
            split_pair(vb.z, vb.w, h1, l1);
            sBh[r * LSTR + lq * 2 + 0] = h0;  sBh[r * LSTR + lq * 2 + 1] = h1;
            sBl[r * LSTR + lq * 2 + 0] = l0;  sBl[r * LSTR + lq * 2 + 1] = l1;
        }
        __syncthreads();

        #pragma unroll
        for (int ks = 0; ks < 2; ks++) {        // two k=16 steps per chunk
            const int kb = ks * 8;              // bf16-pair offset
            uint32_t Ah[4][4], Al[4][4], Bh[4][2], Bl[4][2];

            #pragma unroll
            for (int mt = 0; mt < 4; mt++) {
                const int r = wm * 64 + mt * 16 + g;
                const uint32_t* ph = &sAh[r * LSTR + kb + tg];
                const uint32_t* pl = &sAl[r * LSTR + kb + tg];
                Ah[mt][0] = ph[0];  Ah[mt][1] = ph[8 * LSTR];
                Ah[mt][2] = ph[4];  Ah[mt][3] = ph[8 * LSTR + 4];
                Al[mt][0] = pl[0];  Al[mt][1] = pl[8 * LSTR];
                Al[mt][2] = pl[4];  Al[mt][3] = pl[8 * LSTR + 4];
            }
            #pragma unroll
            for (int nt = 0; nt < 4; nt++) {
                const int n = wn * 32 + nt * 8 + g;
                const uint32_t* ph = &sBh[n * LSTR + kb + tg];
                const uint32_t* pl = &sBl[n * LSTR + kb + tg];
                Bh[nt][0] = ph[0];  Bh[nt][1] = ph[4];
                Bl[nt][0] = pl[0];  Bl[nt][1] = pl[4];
            }

            #pragma unroll
            for (int mt = 0; mt < 4; mt++)
                #pragma unroll
                for (int nt = 0; nt < 4; nt++) {
                    mma_bf16(acc[mt][nt], Ah[mt], Bh[nt]);
                    mma_bf16(acc[mt][nt], Ah[mt], Bl[nt]);
                    mma_bf16(acc[mt][nt], Al[mt], Bh[nt]);
                }
        }
    }

    // epilogue: fragment -> gmem, scaled
    const float scale = 0.08838834764831845f;   // 1/sqrt(128)
    #pragma unroll
    for (int mt = 0; mt < 4; mt++) {
        #pragma unroll
        for (int nt = 0; nt < 4; nt++) {
            const int row = m0 + wm * 64 + mt * 16 + g;
            const int col = j0 + wn * 32 + nt * 8 + tg * 2;
            float* p0 = out + (((size_t)(b * HQ + h)) * NB + row) * NB + col;
            float2 v0 = make_float2(acc[mt][nt][0] * scale, acc[mt][nt][1] * scale);
            *(float2*)p0 = v0;
            float2 v1 = make_float2(acc[mt][nt][2] * scale, acc[mt][nt][3] * scale);
            *(float2*)(p0 + 8 * NB) = v1;
        }
    }
}

// ---------------------------------------------------------------------------
// Kernel 3: in-place masked softmax per row. (unchanged)
// ---------------------------------------------------------------------------
__global__ __launch_bounds__(128)
void softmax_kernel(float* __restrict__ out)
{
    const int row = blockIdx.x;
    const int i   = row & (NB - 1);
    float* p = out + (size_t)row * NB;
    const int t = threadIdx.x;

    float v[4];
    float mx = -3.0e38f;
    #pragma unroll
    for (int jj = 0; jj < 4; jj++) {
        const int j = t + jj * 128;
        v[jj] = (j <= i) ? p[j] : -3.0e38f;
        mx = fmaxf(mx, v[jj]);
    }
    #pragma unroll
    for (int o = 16; o; o >>= 1) mx = fmaxf(mx, __shfl_xor_sync(0xffffffffu, mx, o));

    __shared__ float red[4];
    if ((t & 31) == 0) red[t >> 5] = mx;
    __syncthreads();
    mx = fmaxf(fmaxf(red[0], red[1]), fmaxf(red[2], red[3]));
    __syncthreads();

    float s = 0.f;
    #pragma unroll
    for (int jj = 0; jj < 4; jj++) {
        const int j = t + jj * 128;
        v[jj] = (j <= i) ? expf(v[jj] - mx) : 0.f;
        s += v[jj];
    }
    #pragma unroll
    for (int o = 16; o; o >>= 1) s += __shfl_xor_sync(0xffffffffu, s, o);
    if ((t & 31) == 0) red[t >> 5] = s;
    __syncthreads();
    s = red[0] + red[1] + red[2] + red[3];

    const float inv = 1.0f / s;
    #pragma unroll
    for (int jj = 0; jj < 4; jj++) {
        const int j = t + jj * 128;
        p[j] = v[jj] * inv;
    }
}

// ---------------------------------------------------------------------------
extern "C" void kernel_launch(void* const* d_in, const int* in_sizes, int n_in,
                              void* d_out, int out_size)
{
    const float* q    = (const float*)d_in[0];
    const float* k    = (const float*)d_in[1];
    const float* cosb = (const float*)d_in[3];
    const float* sinb = (const float*)d_in[4];
    const float* wq   = (const float*)d_in[5];
    const float* wk   = (const float*)d_in[6];
    float* out = (float*)d_out;

    // 1) pool + project + rope
    proj_kernel<HQ, true ><<<BB * HQ * (NB / NTILE), 128>>>(q, wq, cosb, sinb);
    proj_kernel<HK, false><<<BB * HK * (NB / NTILE), 128>>>(k, wk, cosb, sinb);

    // 2) causal logits on tensor cores (bf16 split x3, mma.sync)
    dim3 lg(10, HQ, BB);
    logits_mma_kernel<<<lg, 256>>>(out);

    // 3) masked softmax in place
    softmax_kernel<<<BB * HQ * NB, 128>>>(out);
}

// round 10
// speedup vs baseline: 1.9539x; 1.4152x over previous
#include <cuda_runtime.h>
#include <cuda_bf16.h>
#include <cstdint>

// Shapes (fixed by the problem)
#define BB   2
#define HQ   32
#define HK   8
#define SS   8192
#define DD   128
#define HID  128
#define BSZ  16
#define NB   512

// Scratch (allocation-free rule: __device__ globals)
__device__ float g_qh[BB * HQ * NB * HID];   // 16.8 MB
__device__ float g_kh[BB * HK * NB * HID];   //  4.2 MB

// ---------------------------------------------------------------------------
// bf16 split helpers + mma.sync wrapper
// ---------------------------------------------------------------------------
__device__ __forceinline__ void mma_bf16(float* c, const uint32_t* a, const uint32_t* b) {
    asm volatile(
        "mma.sync.aligned.m16n8k16.row.col.f32.bf16.bf16.f32 "
        "{%0,%1,%2,%3}, {%4,%5,%6,%7}, {%8,%9}, {%0,%1,%2,%3};\n"
        : "+f"(c[0]), "+f"(c[1]), "+f"(c[2]), "+f"(c[3])
        : "r"(a[0]), "r"(a[1]), "r"(a[2]), "r"(a[3]), "r"(b[0]), "r"(b[1]));
}

__device__ __forceinline__ void split_pair(float x, float y, uint32_t& hi, uint32_t& lo) {
    __nv_bfloat16 hx = __float2bfloat16(x);
    __nv_bfloat16 hy = __float2bfloat16(y);
    float lx = x - __bfloat162float(hx);
    float ly = y - __bfloat162float(hy);
    __nv_bfloat162 h2 = __halves2bfloat162(hx, hy);          // low half = x-elem
    __nv_bfloat162 l2 = __floats2bfloat162_rn(lx, ly);
    hi = *(uint32_t*)&h2;
    lo = *(uint32_t*)&l2;
}

// ---------------------------------------------------------------------------
// Kernel 1: pool_cat + projection (tensor cores) + RoPE, fused.
// One CTA = 64 n-rows of one (b,h). A = pooled features [64 x 256] (smem,
// bf16 hi/lo, pair stride 132). B = w^T [128 d x 64 cc chunks] (stride 36),
// loaded transposed-coalesced straight from gmem. 3-pass bf16 split MMA.
// Epilogue: fp32 stage in smem -> RoPE -> g_qh / g_kh.
// ---------------------------------------------------------------------------
#define ASTR 132   // A pair stride (== 4 mod 32 -> conflict-free fragments)
#define WSTR 36    // W pair stride (== 4 mod 32)
#define PROJ_SMEM_BYTES ((2 * 64 * ASTR + 2 * 128 * WSTR) * 4)   // 104448

template <int NH, bool IS_Q>
__global__ __launch_bounds__(256)
void proj_mma_kernel(const float* __restrict__ x,
                     const float* __restrict__ w,
                     const float* __restrict__ cosb,
                     const float* __restrict__ sinb)
{
    extern __shared__ uint32_t sm[];
    uint32_t* sAh = sm;
    uint32_t* sAl = sm + 64 * ASTR;
    uint32_t* sWh = sm + 2 * 64 * ASTR;
    uint32_t* sWl = sm + 2 * 64 * ASTR + 128 * WSTR;

    const int bid = blockIdx.x;
    const int mt8 = bid & 7;                 // NB/64 = 8 row tiles
    const int h   = (bid >> 3) % NH;
    const int b   = bid / (8 * NH);
    const int n0  = mt8 * 64;

    const int tid  = threadIdx.x;
    const int lane = tid & 31, wid = tid >> 5;
    const int wm = wid >> 2, wn = wid & 3;   // warp grid 2(m) x 4(n)
    const int g  = lane >> 2, tg = lane & 3;

    // ---- pooling (mean & max over 16 rows) + split into A tile ----
    #pragma unroll
    for (int it = 0; it < 16; it++) {
        const int idx = tid + it * 256;
        const int n  = idx >> 6;             // 0..63
        const int dp = idx & 63;             // d/2
        const float* xp = x + (((size_t)(b * NH + h)) * SS + (size_t)(n0 + n) * BSZ) * DD + dp * 2;
        float2 s  = make_float2(0.f, 0.f);
        float2 mx = make_float2(-3.0e38f, -3.0e38f);
        #pragma unroll
        for (int i = 0; i < BSZ; i++) {
            float2 v = *(const float2*)&xp[i * DD];
            s.x += v.x;  s.y += v.y;
            mx.x = fmaxf(mx.x, v.x);  mx.y = fmaxf(mx.y, v.y);
        }
        uint32_t hh, ll;
        split_pair(s.x * (1.0f / BSZ), s.y * (1.0f / BSZ), hh, ll);
        sAh[n * ASTR + dp] = hh;  sAl[n * ASTR + dp] = ll;
        split_pair(mx.x, mx.y, hh, ll);
        sAh[n * ASTR + 64 + dp] = hh;  sAl[n * ASTR + 64 + dp] = ll;
    }
    __syncthreads();

    float acc[2][4][4];
    #pragma unroll
    for (int i = 0; i < 2; i++)
        #pragma unroll
        for (int j = 0; j < 4; j++)
            #pragma unroll
            for (int r = 0; r < 4; r++) acc[i][j][r] = 0.f;

    for (int kc = 0; kc < 4; kc++) {         // 4 chunks of 64 cc
        // ---- load W chunk transposed from gmem, split bf16 ----
        #pragma unroll
        for (int it = 0; it < 16; it++) {
            const int idx = tid + it * 256;
            const int d  = idx & 127;
            const int cp = idx >> 7;         // 0..31 (cc pair within chunk)
            const int cc = kc * 64 + cp * 2;
            const float* wp2 = w + ((size_t)h * 256 + cc) * 128 + d;
            uint32_t hh, ll;
            split_pair(wp2[0], wp2[128], hh, ll);
            sWh[d * WSTR + cp] = hh;
            sWl[d * WSTR + cp] = ll;
        }
        __syncthreads();

        #pragma unroll
        for (int ksl = 0; ksl < 4; ksl++) {  // k16 steps within chunk
            const int ka = (kc * 4 + ksl) * 8;   // A pair offset (full K)
            const int kb = ksl * 8;              // W pair offset (chunk)
            uint32_t Ah[2][4], Al[2][4], Bh[4][2], Bl[4][2];

            #pragma unroll
            for (int mt = 0; mt < 2; mt++) {
                const uint32_t* ph = &sAh[(wm * 32 + mt * 16 + g) * ASTR + ka + tg];
                const uint32_t* pl = &sAl[(wm * 32 + mt * 16 + g) * ASTR + ka + tg];
                Ah[mt][0] = ph[0];  Ah[mt][1] = ph[8 * ASTR];
                Ah[mt][2] = ph[4];  Ah[mt][3] = ph[8 * ASTR + 4];
                Al[mt][0] = pl[0];  Al[mt][1] = pl[8 * ASTR];
                Al[mt][2] = pl[4];  Al[mt][3] = pl[8 * ASTR + 4];
            }
            #pragma unroll
            for (int nt = 0; nt < 4; nt++) {
                const uint32_t* ph = &sWh[(wn * 32 + nt * 8 + g) * WSTR + kb + tg];
                const uint32_t* pl = &sWl[(wn * 32 + nt * 8 + g) * WSTR + kb + tg];
                Bh[nt][0] = ph[0];  Bh[nt][1] = ph[4];
                Bl[nt][0] = pl[0];  Bl[nt][1] = pl[4];
            }

            #pragma unroll
            for (int mt = 0; mt < 2; mt++)
                #pragma unroll
                for (int nt = 0; nt < 4; nt++) {
                    mma_bf16(acc[mt][nt], Ah[mt], Bh[nt]);
                    mma_bf16(acc[mt][nt], Ah[mt], Bl[nt]);
                    mma_bf16(acc[mt][nt], Al[mt], Bh[nt]);
                }
        }
        __syncthreads();
    }

    // ---- epilogue: stage fp32 tile, RoPE, write ----
    float* stage = (float*)sm;               // 64 x ASTR floats (fits in sAh+sAl)
    #pragma unroll
    for (int mt = 0; mt < 2; mt++)
        #pragma unroll
        for (int nt = 0; nt < 4; nt++) {
            const int row = wm * 32 + mt * 16 + g;
            const int col = wn * 32 + nt * 8 + tg * 2;
            stage[row * ASTR + col]           = acc[mt][nt][0];
            stage[row * ASTR + col + 1]       = acc[mt][nt][1];
            stage[(row + 8) * ASTR + col]     = acc[mt][nt][2];
            stage[(row + 8) * ASTR + col + 1] = acc[mt][nt][3];
        }
    __syncthreads();

    float* dst = IS_Q ? g_qh : g_kh;
    #pragma unroll
    for (int it = 0; it < 16; it++) {
        const int idx = tid + it * 256;
        const int n  = idx >> 6;
        const int d  = (idx & 63) * 2;
        float2 v = *(const float2*)&stage[n * ASTR + d];
        float2 r;
        if (d < 64) {
            r.x = -stage[n * ASTR + d + 64];
            r.y = -stage[n * ASTR + d + 65];
        } else {
            r.x = stage[n * ASTR + d - 64];
            r.y = stage[n * ASTR + d - 63];
        }
        const size_t ci = ((size_t)b * NB + n0 + n) * HID + d;
        float2 c  = *(const float2*)&cosb[ci];
        float2 sn = *(const float2*)&sinb[ci];
        float2 o;
        o.x = v.x * c.x + r.x * sn.x;
        o.y = v.y * c.y + r.y * sn.y;
        *(float2*)&dst[(((size_t)(b * NH + h)) * NB + n0 + n) * HID + d] = o;
    }
}

// ---------------------------------------------------------------------------
// Kernel 2: block-causal logits via mma.sync bf16 split (unchanged from R8).
// ---------------------------------------------------------------------------
#define LSTR 20

__global__ __launch_bounds__(256, 1)
void logits_mma_kernel(float* __restrict__ out)
{
    __shared__ uint32_t sAh[128 * LSTR], sAl[128 * LSTR];
    __shared__ uint32_t sBh[128 * LSTR], sBl[128 * LSTR];

    const int b  = blockIdx.z;
    const int h  = blockIdx.y;
    const int ti = blockIdx.x;
    const int mt4 = (ti >= 6) ? 3 : (ti >= 3) ? 2 : (ti >= 1) ? 1 : 0;
    const int jt  = ti - mt4 * (mt4 + 1) / 2;
    const int m0  = mt4 * 128;
    const int j0  = jt * 128;

    const float* Ag = g_qh + (((size_t)(b * HQ + h)) * NB + m0) * HID;
    const float* Bg = g_kh + (((size_t)(b * HK + h / (HQ / HK))) * NB + j0) * HID;

    const int tid  = threadIdx.x;
    const int lane = tid & 31, wid = tid >> 5;
    const int wm = wid >> 2, wn = wid & 3;
    const int g  = lane >> 2, tg = lane & 3;

    float acc[4][4][4];
    #pragma unroll
    for (int i = 0; i < 4; i++)
        #pragma unroll
        for (int j = 0; j < 4; j++)
            #pragma unroll
            for (int r = 0; r < 4; r++) acc[i][j][r] = 0.f;

    const int lr0 = tid >> 3;
    const int lq  = tid & 7;

    for (int kc = 0; kc < 4; kc++) {
        __syncthreads();
        #pragma unroll
        for (int pass = 0; pass < 4; pass++) {
            const int r = pass * 32 + lr0;
            float4 va = *(const float4*)&Ag[(size_t)r * HID + kc * 32 + lq * 4];
            uint32_t h0, l0, h1, l1;
            split_pair(va.x, va.y, h0, l0);
            split_pair(va.z, va.w, h1, l1);
            sAh[r * LSTR + lq * 2 + 0] = h0;  sAh[r * LSTR + lq * 2 + 1] = h1;
            sAl[r * LSTR + lq * 2 + 0] = l0;  sAl[r * LSTR + lq * 2 + 1] = l1;

            float4 vb = *(const float4*)&Bg[(size_t)r * HID + kc * 32 + lq * 4];
            split_pair(vb.x, vb.y, h0, l0);
            split_pair(vb.z, vb.w, h1, l1);
            sBh[r * LSTR + lq * 2 + 0] = h0;  sBh[r * LSTR + lq * 2 + 1] = h1;
            sBl[r * LSTR + lq * 2 + 0] = l0;  sBl[r * LSTR + lq * 2 + 1] = l1;
        }
        __syncthreads();

        #pragma unroll
        for (int ks = 0; ks < 2; ks++) {
            const int kb = ks * 8;
            uint32_t Ah[4][4], Al[4][4], Bh[4][2], Bl[4][2];

            #pragma unroll
            for (int mt = 0; mt < 4; mt++) {
                const int r = wm * 64 + mt * 16 + g;
                const uint32_t* ph = &sAh[r * LSTR + kb + tg];
                const uint32_t* pl = &sAl[r * LSTR + kb + tg];
                Ah[mt][0] = ph[0];  Ah[mt][1] = ph[8 * LSTR];
                Ah[mt][2] = ph[4];  Ah[mt][3] = ph[8 * LSTR + 4];
                Al[mt][0] = pl[0];  Al[mt][1] = pl[8 * LSTR];
                Al[mt][2] = pl[4];  Al[mt][3] = pl[8 * LSTR + 4];
            }
            #pragma unroll
            for (int nt = 0; nt < 4; nt++) {
                const int n = wn * 32 + nt * 8 + g;
                const uint32_t* ph = &sBh[n * LSTR + kb + tg];
                const uint32_t* pl = &sBl[n * LSTR + kb + tg];
                Bh[nt][0] = ph[0];  Bh[nt][1] = ph[4];
                Bl[nt][0] = pl[0];  Bl[nt][1] = pl[4];
            }

            #pragma unroll
            for (int mt = 0; mt < 4; mt++)
                #pragma unroll
                for (int nt = 0; nt < 4; nt++) {
                    mma_bf16(acc[mt][nt], Ah[mt], Bh[nt]);
                    mma_bf16(acc[mt][nt], Ah[mt], Bl[nt]);
                    mma_bf16(acc[mt][nt], Al[mt], Bh[nt]);
                }
        }
    }

    const float scale = 0.08838834764831845f;
    #pragma unroll
    for (int mt = 0; mt < 4; mt++) {
        #pragma unroll
        for (int nt = 0; nt < 4; nt++) {
            const int row = m0 + wm * 64 + mt * 16 + g;
            const int col = j0 + wn * 32 + nt * 8 + tg * 2;
            float* p0 = out + (((size_t)(b * HQ + h)) * NB + row) * NB + col;
            *(float2*)p0 = make_float2(acc[mt][nt][0] * scale, acc[mt][nt][1] * scale);
            *(float2*)(p0 + 8 * NB) = make_float2(acc[mt][nt][2] * scale, acc[mt][nt][3] * scale);
        }
    }
}

// ---------------------------------------------------------------------------
// Kernel 3: in-place masked softmax per row. (unchanged)
// ---------------------------------------------------------------------------
__global__ __launch_bounds__(128)
void softmax_kernel(float* __restrict__ out)
{
    const int row = blockIdx.x;
    const int i   = row & (NB - 1);
    float* p = out + (size_t)row * NB;
    const int t = threadIdx.x;

    float v[4];
    float mx = -3.0e38f;
    #pragma unroll
    for (int jj = 0; jj < 4; jj++) {
        const int j = t + jj * 128;
        v[jj] = (j <= i) ? p[j] : -3.0e38f;
        mx = fmaxf(mx, v[jj]);
    }
    #pragma unroll
    for (int o = 16; o; o >>= 1) mx = fmaxf(mx, __shfl_xor_sync(0xffffffffu, mx, o));

    __shared__ float red[4];
    if ((t & 31) == 0) red[t >> 5] = mx;
    __syncthreads();
    mx = fmaxf(fmaxf(red[0], red[1]), fmaxf(red[2], red[3]));
    __syncthreads();

    float s = 0.f;
    #pragma unroll
    for (int jj = 0; jj < 4; jj++) {
        const int j = t + jj * 128;
        v[jj] = (j <= i) ? expf(v[jj] - mx) : 0.f;
        s += v[jj];
    }
    #pragma unroll
    for (int o = 16; o; o >>= 1) s += __shfl_xor_sync(0xffffffffu, s, o);
    if ((t & 31) == 0) red[t >> 5] = s;
    __syncthreads();
    s = red[0] + red[1] + red[2] + red[3];

    const float inv = 1.0f / s;
    #pragma unroll
    for (int jj = 0; jj < 4; jj++) {
        const int j = t + jj * 128;
        p[j] = v[jj] * inv;
    }
}

// ---------------------------------------------------------------------------
extern "C" void kernel_launch(void* const* d_in, const int* in_sizes, int n_in,
                              void* d_out, int out_size)
{
    const float* q    = (const float*)d_in[0];
    const float* k    = (const float*)d_in[1];
    const float* cosb = (const float*)d_in[3];
    const float* sinb = (const float*)d_in[4];
    const float* wq   = (const float*)d_in[5];
    const float* wk   = (const float*)d_in[6];
    float* out = (float*)d_out;

    cudaFuncSetAttribute(proj_mma_kernel<HQ, true>,
                         cudaFuncAttributeMaxDynamicSharedMemorySize, PROJ_SMEM_BYTES);
    cudaFuncSetAttribute(proj_mma_kernel<HK, false>,
                         cudaFuncAttributeMaxDynamicSharedMemorySize, PROJ_SMEM_BYTES);

    // 1) pool + project (tensor) + rope
    proj_mma_kernel<HQ, true ><<<BB * HQ * 8, 256, PROJ_SMEM_BYTES>>>(q, wq, cosb, sinb);
    proj_mma_kernel<HK, false><<<BB * HK * 8, 256, PROJ_SMEM_BYTES>>>(k, wk, cosb, sinb);

    // 2) causal logits on tensor cores (bf16 split x3, mma.sync)
    dim3 lg(10, HQ, BB);
    logits_mma_kernel<<<lg, 256>>>(out);

    // 3) masked softmax in place
    softmax_kernel<<<BB * HQ * NB, 128>>>(out);
}

// round 13
// speedup vs baseline: 2.0948x; 1.0721x over previous
#include <cuda_runtime.h>
#include <cuda_bf16.h>
#include <cstdint>

// Shapes (fixed by the problem)
#define BB   2
#define HQ   32
#define HK   8
#define SS   8192
#define DD   128
#define HID  128
#define BSZ  16
#define NB   512

// Scratch (allocation-free rule: __device__ globals)
__device__ float g_qh[BB * HQ * NB * HID];   // 16.8 MB
__device__ float g_kh[BB * HK * NB * HID];   //  4.2 MB

// ---------------------------------------------------------------------------
// bf16 split helpers + mma.sync wrapper
// ---------------------------------------------------------------------------
__device__ __forceinline__ void mma_bf16(float* c, const uint32_t* a, const uint32_t* b) {
    asm volatile(
        "mma.sync.aligned.m16n8k16.row.col.f32.bf16.bf16.f32 "
        "{%0,%1,%2,%3}, {%4,%5,%6,%7}, {%8,%9}, {%0,%1,%2,%3};\n"
        : "+f"(c[0]), "+f"(c[1]), "+f"(c[2]), "+f"(c[3])
        : "r"(a[0]), "r"(a[1]), "r"(a[2]), "r"(a[3]), "r"(b[0]), "r"(b[1]));
}

__device__ __forceinline__ void split_pair(float x, float y, uint32_t& hi, uint32_t& lo) {
    __nv_bfloat16 hx = __float2bfloat16(x);
    __nv_bfloat16 hy = __float2bfloat16(y);
    float lx = x - __bfloat162float(hx);
    float ly = y - __bfloat162float(hy);
    __nv_bfloat162 h2 = __halves2bfloat162(hx, hy);          // low half = x-elem
    __nv_bfloat162 l2 = __floats2bfloat162_rn(lx, ly);
    hi = *(uint32_t*)&h2;
    lo = *(uint32_t*)&l2;
}

// ---------------------------------------------------------------------------
// Kernel 1: pool_cat + projection (tensor cores) + RoPE, fused; Q and K parts
// merged into ONE launch (k-blocks scheduled last, backfilling the q tail).
// One CTA = 64 n-rows of one (b,h). 2 CTAs/SM so pooling (DRAM) of one CTA
// overlaps MMA of the other.
// ---------------------------------------------------------------------------
#define ASTR 132   // A pair stride (== 4 mod 32 -> conflict-free fragments)
#define WSTR 36    // W pair stride (== 4 mod 32)
#define PROJ_SMEM_BYTES ((2 * 64 * ASTR + 2 * 128 * WSTR) * 4)   // 104448

__global__ __launch_bounds__(256, 2)
void proj_mma_kernel(const float* __restrict__ q,
                     const float* __restrict__ kk,
                     const float* __restrict__ wq,
                     const float* __restrict__ wk,
                     const float* __restrict__ cosb,
                     const float* __restrict__ sinb)
{
    extern __shared__ uint32_t sm[];
    uint32_t* sAh = sm;
    uint32_t* sAl = sm + 64 * ASTR;
    uint32_t* sWh = sm + 2 * 64 * ASTR;
    uint32_t* sWl = sm + 2 * 64 * ASTR + 128 * WSTR;

    const int bid0 = blockIdx.x;
    const bool isQ = bid0 < BB * HQ * 8;
    const int bid  = isQ ? bid0 : bid0 - BB * HQ * 8;
    const int NH   = isQ ? HQ : HK;
    const float* x = isQ ? q  : kk;
    const float* w = isQ ? wq : wk;
    float* dst     = isQ ? g_qh : g_kh;

    const int mt8 = bid & 7;                 // NB/64 = 8 row tiles
    const int h   = (bid >> 3) % NH;
    const int b   = bid / (8 * NH);
    const int n0  = mt8 * 64;

    const int tid  = threadIdx.x;
    const int lane = tid & 31, wid = tid >> 5;
    const int wm = wid >> 2, wn = wid & 3;   // warp grid 2(m) x 4(n)
    const int g  = lane >> 2, tg = lane & 3;

    // ---- pooling (mean & max over 16 rows) + split into A tile ----
    // warp covers one n-row (32 lanes x float4 = 128 floats); 8 n per pass
    {
        const int q4 = lane;                 // float4 index 0..31
        #pragma unroll
        for (int nt = 0; nt < 8; nt++) {
            const int n = nt * 8 + wid;
            const float* xp = x + (((size_t)(b * NH + h)) * SS + (size_t)(n0 + n) * BSZ) * DD + q4 * 4;
            float4 s  = make_float4(0.f, 0.f, 0.f, 0.f);
            float4 mx = make_float4(-3.0e38f, -3.0e38f, -3.0e38f, -3.0e38f);
            #pragma unroll
            for (int i = 0; i < BSZ; i++) {
                float4 v = *(const float4*)&xp[i * DD];
                s.x += v.x;  s.y += v.y;  s.z += v.z;  s.w += v.w;
                mx.x = fmaxf(mx.x, v.x);  mx.y = fmaxf(mx.y, v.y);
                mx.z = fmaxf(mx.z, v.z);  mx.w = fmaxf(mx.w, v.w);
            }
            uint32_t hh, ll;
            split_pair(s.x * (1.0f / BSZ), s.y * (1.0f / BSZ), hh, ll);
            sAh[n * ASTR + q4 * 2]     = hh;  sAl[n * ASTR + q4 * 2]     = ll;
            split_pair(s.z * (1.0f / BSZ), s.w * (1.0f / BSZ), hh, ll);
            sAh[n * ASTR + q4 * 2 + 1] = hh;  sAl[n * ASTR + q4 * 2 + 1] = ll;
            split_pair(mx.x, mx.y, hh, ll);
            sAh[n * ASTR + 64 + q4 * 2]     = hh;  sAl[n * ASTR + 64 + q4 * 2]     = ll;
            split_pair(mx.z, mx.w, hh, ll);
            sAh[n * ASTR + 64 + q4 * 2 + 1] = hh;  sAl[n * ASTR + 64 + q4 * 2 + 1] = ll;
        }
    }
    __syncthreads();

    float acc[2][4][4];
    #pragma unroll
    for (int i = 0; i < 2; i++)
        #pragma unroll
        for (int j = 0; j < 4; j++)
            #pragma unroll
            for (int r = 0; r < 4; r++) acc[i][j][r] = 0.f;

    for (int kc = 0; kc < 4; kc++) {         // 4 chunks of 64 cc
        // ---- load W chunk transposed from gmem, split bf16 ----
        #pragma unroll
        for (int it = 0; it < 16; it++) {
            const int idx = tid + it * 256;
            const int d  = idx & 127;
            const int cp = idx >> 7;         // 0..31 (cc pair within chunk)
            const int cc = kc * 64 + cp * 2;
            const float* wp2 = w + ((size_t)h * 256 + cc) * 128 + d;
            uint32_t hh, ll;
            split_pair(wp2[0], wp2[128], hh, ll);
            sWh[d * WSTR + cp] = hh;
            sWl[d * WSTR + cp] = ll;
        }
        __syncthreads();

        #pragma unroll
        for (int ksl = 0; ksl < 4; ksl++) {  // k16 steps within chunk
            const int ka = (kc * 4 + ksl) * 8;   // A pair offset (full K)
            const int kb = ksl * 8;              // W pair offset (chunk)
            uint32_t Ah[2][4], Al[2][4], Bh[4][2], Bl[4][2];

            #pragma unroll
            for (int mt = 0; mt < 2; mt++) {
                const uint32_t* ph = &sAh[(wm * 32 + mt * 16 + g) * ASTR + ka + tg];
                const uint32_t* pl = &sAl[(wm * 32 + mt * 16 + g) * ASTR + ka + tg];
                Ah[mt][0] = ph[0];  Ah[mt][1] = ph[8 * ASTR];
                Ah[mt][2] = ph[4];  Ah[mt][3] = ph[8 * ASTR + 4];
                Al[mt][0] = pl[0];  Al[mt][1] = pl[8 * ASTR];
                Al[mt][2] = pl[4];  Al[mt][3] = pl[8 * ASTR + 4];
            }
            #pragma unroll
            for (int nt = 0; nt < 4; nt++) {
                const uint32_t* ph = &sWh[(wn * 32 + nt * 8 + g) * WSTR + kb + tg];
                const uint32_t* pl = &sWl[(wn * 32 + nt * 8 + g) * WSTR + kb + tg];
                Bh[nt][0] = ph[0];  Bh[nt][1] = ph[4];
                Bl[nt][0] = pl[0];  Bl[nt][1] = pl[4];
            }

            #pragma unroll
            for (int mt = 0; mt < 2; mt++)
                #pragma unroll
                for (int nt = 0; nt < 4; nt++) {
                    mma_bf16(acc[mt][nt], Ah[mt], Bh[nt]);
                    mma_bf16(acc[mt][nt], Ah[mt], Bl[nt]);
                    mma_bf16(acc[mt][nt], Al[mt], Bh[nt]);
                }
        }
        __syncthreads();
    }

    // ---- epilogue: stage fp32 tile, RoPE, write ----
    float* stage = (float*)sm;               // 64 x ASTR floats (fits in sAh+sAl)
    #pragma unroll
    for (int mt = 0; mt < 2; mt++)
        #pragma unroll
        for (int nt = 0; nt < 4; nt++) {
            const int row = wm * 32 + mt * 16 + g;
            const int col = wn * 32 + nt * 8 + tg * 2;
            stage[row * ASTR + col]           = acc[mt][nt][0];
            stage[row * ASTR + col + 1]       = acc[mt][nt][1];
            stage[(row + 8) * ASTR + col]     = acc[mt][nt][2];
            stage[(row + 8) * ASTR + col + 1] = acc[mt][nt][3];
        }
    __syncthreads();

    #pragma unroll
    for (int it = 0; it < 16; it++) {
        const int idx = tid + it * 256;
        const int n  = idx >> 6;
        const int d  = (idx & 63) * 2;
        float2 v = *(const float2*)&stage[n * ASTR + d];
        float2 r;
        if (d < 64) {
            r.x = -stage[n * ASTR + d + 64];
            r.y = -stage[n * ASTR + d + 65];
        } else {
            r.x = stage[n * ASTR + d - 64];
            r.y = stage[n * ASTR + d - 63];
        }
        const size_t ci = ((size_t)b * NB + n0 + n) * HID + d;
        float2 c  = *(const float2*)&cosb[ci];
        float2 sn = *(const float2*)&sinb[ci];
        float2 o;
        o.x = v.x * c.x + r.x * sn.x;
        o.y = v.y * c.y + r.y * sn.y;
        *(float2*)&dst[(((size_t)(b * NH + h)) * NB + n0 + n) * HID + d] = o;
    }
}

// ---------------------------------------------------------------------------
// Kernel 2: block-causal logits via mma.sync bf16 split (unchanged).
// ---------------------------------------------------------------------------
#define LSTR 20

__global__ __launch_bounds__(256, 1)
void logits_mma_kernel(float* __restrict__ out)
{
    __shared__ uint32_t sAh[128 * LSTR], sAl[128 * LSTR];
    __shared__ uint32_t sBh[128 * LSTR], sBl[128 * LSTR];

    const int b  = blockIdx.z;
    const int h  = blockIdx.y;
    const int ti = blockIdx.x;
    const int mt4 = (ti >= 6) ? 3 : (ti >= 3) ? 2 : (ti >= 1) ? 1 : 0;
    const int jt  = ti - mt4 * (mt4 + 1) / 2;
    const int m0  = mt4 * 128;
    const int j0  = jt * 128;

    const float* Ag = g_qh + (((size_t)(b * HQ + h)) * NB + m0) * HID;
    const float* Bg = g_kh + (((size_t)(b * HK + h / (HQ / HK))) * NB + j0) * HID;

    const int tid  = threadIdx.x;
    const int lane = tid & 31, wid = tid >> 5;
    const int wm = wid >> 2, wn = wid & 3;
    const int g  = lane >> 2, tg = lane & 3;

    float acc[4][4][4];
    #pragma unroll
    for (int i = 0; i < 4; i++)
        #pragma unroll
        for (int j = 0; j < 4; j++)
            #pragma unroll
            for (int r = 0; r < 4; r++) acc[i][j][r] = 0.f;

    const int lr0 = tid >> 3;
    const int lq  = tid & 7;

    for (int kc = 0; kc < 4; kc++) {
        __syncthreads();
        #pragma unroll
        for (int pass = 0; pass < 4; pass++) {
            const int r = pass * 32 + lr0;
            float4 va = *(const float4*)&Ag[(size_t)r * HID + kc * 32 + lq * 4];
            uint32_t h0, l0, h1, l1;
            split_pair(va.x, va.y, h0, l0);
            split_pair(va.z, va.w, h1, l1);
            sAh[r * LSTR + lq * 2 + 0] = h0;  sAh[r * LSTR + lq * 2 + 1] = h1;
            sAl[r * LSTR + lq * 2 + 0] = l0;  sAl[r * LSTR + lq * 2 + 1] = l1;

            float4 vb = *(const float4*)&Bg[(size_t)r * HID + kc * 32 + lq * 4];
            split_pair(vb.x, vb.y, h0, l0);
            split_pair(vb.z, vb.w, h1, l1);
            sBh[r * LSTR + lq * 2 + 0] = h0;  sBh[r * LSTR + lq * 2 + 1] = h1;
            sBl[r * LSTR + lq * 2 + 0] = l0;  sBl[r * LSTR + lq * 2 + 1] = l1;
        }
        __syncthreads();

        #pragma unroll
        for (int ks = 0; ks < 2; ks++) {
            const int kb = ks * 8;
            uint32_t Ah[4][4], Al[4][4], Bh[4][2], Bl[4][2];

            #pragma unroll
            for (int mt = 0; mt < 4; mt++) {
                const int r = wm * 64 + mt * 16 + g;
                const uint32_t* ph = &sAh[r * LSTR + kb + tg];
                const uint32_t* pl = &sAl[r * LSTR + kb + tg];
                Ah[mt][0] = ph[0];  Ah[mt][1] = ph[8 * LSTR];
                Ah[mt][2] = ph[4];  Ah[mt][3] = ph[8 * LSTR + 4];
                Al[mt][0] = pl[0];  Al[mt][1] = pl[8 * LSTR];
                Al[mt][2] = pl[4];  Al[mt][3] = pl[8 * LSTR + 4];
            }
            #pragma unroll
            for (int nt = 0; nt < 4; nt++) {
                const int n = wn * 32 + nt * 8 + g;
                const uint32_t* ph = &sBh[n * LSTR + kb + tg];
                const uint32_t* pl = &sBl[n * LSTR + kb + tg];
                Bh[nt][0] = ph[0];  Bh[nt][1] = ph[4];
                Bl[nt][0] = pl[0];  Bl[nt][1] = pl[4];
            }

            #pragma unroll
            for (int mt = 0; mt < 4; mt++)
                #pragma unroll
                for (int nt = 0; nt < 4; nt++) {
                    mma_bf16(acc[mt][nt], Ah[mt], Bh[nt]);
                    mma_bf16(acc[mt][nt], Ah[mt], Bl[nt]);
                    mma_bf16(acc[mt][nt], Al[mt], Bh[nt]);
                }
        }
    }

    const float scale = 0.08838834764831845f;
    #pragma unroll
    for (int mt = 0; mt < 4; mt++) {
        #pragma unroll
        for (int nt = 0; nt < 4; nt++) {
            const int row = m0 + wm * 64 + mt * 16 + g;
            const int col = j0 + wn * 32 + nt * 8 + tg * 2;
            float* p0 = out + (((size_t)(b * HQ + h)) * NB + row) * NB + col;
            *(float2*)p0 = make_float2(acc[mt][nt][0] * scale, acc[mt][nt][1] * scale);
            *(float2*)(p0 + 8 * NB) = make_float2(acc[mt][nt][2] * scale, acc[mt][nt][3] * scale);
        }
    }
}

// ---------------------------------------------------------------------------
// Kernel 3: masked softmax, one WARP per row (shuffle-only reductions, no
// __syncthreads, no smem). 512 threads = 16 rows per block.
// ---------------------------------------------------------------------------
__global__ __launch_bounds__(512)
void softmax_kernel(float* __restrict__ out)
{
    const int wid  = threadIdx.x >> 5;
    const int lane = threadIdx.x & 31;
    const int row  = blockIdx.x * 16 + wid;      // ((b*HQ+h)*NB + i)
    const int i    = row & (NB - 1);
    float* p = out + (size_t)row * NB;

    float4 v[4];
    float mx = -3.0e38f;
    #pragma unroll
    for (int w = 0; w < 4; w++) {
        const int j = w * 128 + lane * 4;
        if (j <= i) {
            v[w] = *(const float4*)&p[j];
            if (j + 1 > i) v[w].y = -3.0e38f;
            if (j + 2 > i) v[w].z = -3.0e38f;
            if (j + 3 > i) v[w].w = -3.0e38f;
        } else {
            v[w] = make_float4(-3.0e38f, -3.0e38f, -3.0e38f, -3.0e38f);
        }
        mx = fmaxf(mx, fmaxf(fmaxf(v[w].x, v[w].y), fmaxf(v[w].z, v[w].w)));
    }
    #pragma unroll
    for (int o = 16; o; o >>= 1) mx = fmaxf(mx, __shfl_xor_sync(0xffffffffu, mx, o));

    float s = 0.f;
    #pragma unroll
    for (int w = 0; w < 4; w++) {
        v[w].x = (v[w].x > -1.0e38f) ? expf(v[w].x - mx) : 0.f;
        v[w].y = (v[w].y > -1.0e38f) ? expf(v[w].y - mx) : 0.f;
        v[w].z = (v[w].z > -1.0e38f) ? expf(v[w].z - mx) : 0.f;
        v[w].w = (v[w].w > -1.0e38f) ? expf(v[w].w - mx) : 0.f;
        s += v[w].x + v[w].y + v[w].z + v[w].w;
    }
    #pragma unroll
    for (int o = 16; o; o >>= 1) s += __shfl_xor_sync(0xffffffffu, s, o);

    const float inv = 1.0f / s;
    #pragma unroll
    for (int w = 0; w < 4; w++) {
        float4 o4;
        o4.x = v[w].x * inv;  o4.y = v[w].y * inv;
        o4.z = v[w].z * inv;  o4.w = v[w].w * inv;
        *(float4*)&p[w * 128 + lane * 4] = o4;
    }
}

// ---------------------------------------------------------------------------
extern "C" void kernel_launch(void* const* d_in, const int* in_sizes, int n_in,
                              void* d_out, int out_size)
{
    const float* q    = (const float*)d_in[0];
    const float* k    = (const float*)d_in[1];
    const float* cosb = (const float*)d_in[3];
    const float* sinb = (const float*)d_in[4];
    const float* wq   = (const float*)d_in[5];
    const float* wk   = (const float*)d_in[6];
    float* out = (float*)d_out;

    cudaFuncSetAttribute(proj_mma_kernel,
                         cudaFuncAttributeMaxDynamicSharedMemorySize, PROJ_SMEM_BYTES);

    // 1) pool + project (tensor) + rope — q and k merged into one grid
    proj_mma_kernel<<<BB * HQ * 8 + BB * HK * 8, 256, PROJ_SMEM_BYTES>>>(
        q, k, wq, wk, cosb, sinb);

    // 2) causal logits on tensor cores (bf16 split x3, mma.sync)
    dim3 lg(10, HQ, BB);
    logits_mma_kernel<<<lg, 256>>>(out);

    // 3) masked softmax in place (warp per row)
    softmax_kernel<<<BB * HQ * NB / 16, 512>>>(out);
}

// round 15
// speedup vs baseline: 2.1023x; 1.0036x over previous
#include <cuda_runtime.h>
#include <cuda_bf16.h>
#include <cstdint>

// Shapes (fixed by the problem)
#define BB   2
#define HQ   32
#define HK   8
#define SS   8192
#define DD   128
#define HID  128
#define BSZ  16
#define NB   512

// Scratch (allocation-free rule: __device__ globals)
__device__ float g_qh[BB * HQ * NB * HID];     // 16.8 MB
__device__ float g_kh[BB * HK * NB * HID];     //  4.2 MB
__device__ float g_pq[BB * HQ * NB * 256];     // 33.5 MB pooled q (mean||max)
__device__ float g_pk[BB * HK * NB * 256];     //  8.4 MB pooled k

// ---------------------------------------------------------------------------
// bf16 split helpers + mma.sync wrapper
// ---------------------------------------------------------------------------
__device__ __forceinline__ void mma_bf16(float* c, const uint32_t* a, const uint32_t* b) {
    asm volatile(
        "mma.sync.aligned.m16n8k16.row.col.f32.bf16.bf16.f32 "
        "{%0,%1,%2,%3}, {%4,%5,%6,%7}, {%8,%9}, {%0,%1,%2,%3};\n"
        : "+f"(c[0]), "+f"(c[1]), "+f"(c[2]), "+f"(c[3])
        : "r"(a[0]), "r"(a[1]), "r"(a[2]), "r"(a[3]), "r"(b[0]), "r"(b[1]));
}

__device__ __forceinline__ void split_pair(float x, float y, uint32_t& hi, uint32_t& lo) {
    __nv_bfloat16 hx = __float2bfloat16(x);
    __nv_bfloat16 hy = __float2bfloat16(y);
    float lx = x - __bfloat162float(hx);
    float ly = y - __bfloat162float(hy);
    __nv_bfloat162 h2 = __halves2bfloat162(hx, hy);          // low half = x-elem
    __nv_bfloat162 l2 = __floats2bfloat162_rn(lx, ly);
    hi = *(uint32_t*)&h2;
    lo = *(uint32_t*)&l2;
}

// ---------------------------------------------------------------------------
// Kernel 0: pooling (mean & max over BSZ=16 rows), pure streaming at full
// occupancy. One thread = 4 d's of one (b,h,n): 16 independent float4 loads.
// Writes pooled [b,h,n,0:128]=mean, [128:256]=max.
// ---------------------------------------------------------------------------
__global__ __launch_bounds__(256)
void pool_kernel(const float* __restrict__ q, const float* __restrict__ kk)
{
    int idx = blockIdx.x * 256 + threadIdx.x;
    const float* x;
    float* dst;
    int NH;
    if (idx < BB * HQ * NB * 32) {
        x = q;  dst = g_pq;  NH = HQ;
    } else {
        idx -= BB * HQ * NB * 32;
        x = kk; dst = g_pk;  NH = HK;
    }
    const int d4 = idx & 31;
    const int n  = (idx >> 5) & (NB - 1);
    const int hb = idx >> 14;
    const int h  = hb % NH;
    const int b  = hb / NH;

    const float* xp = x + (((size_t)(b * NH + h)) * SS + (size_t)n * BSZ) * DD + d4 * 4;
    float4 s  = make_float4(0.f, 0.f, 0.f, 0.f);
    float4 mx = make_float4(-3.0e38f, -3.0e38f, -3.0e38f, -3.0e38f);
    #pragma unroll
    for (int i = 0; i < BSZ; i++) {
        float4 v = *(const float4*)&xp[i * DD];
        s.x += v.x;  s.y += v.y;  s.z += v.z;  s.w += v.w;
        mx.x = fmaxf(mx.x, v.x);  mx.y = fmaxf(mx.y, v.y);
        mx.z = fmaxf(mx.z, v.z);  mx.w = fmaxf(mx.w, v.w);
    }
    float* o = dst + (((size_t)(b * NH + h)) * NB + n) * 256;
    float4 mn = make_float4(s.x * (1.0f / BSZ), s.y * (1.0f / BSZ),
                            s.z * (1.0f / BSZ), s.w * (1.0f / BSZ));
    *(float4*)&o[d4 * 4]       = mn;
    *(float4*)&o[128 + d4 * 4] = mx;
}

// ---------------------------------------------------------------------------
// Kernel 1: projection (tensor cores) + RoPE, reading pooled features.
// Q and K merged into one launch. One CTA = 64 n-rows of one (b,h).
// ---------------------------------------------------------------------------
#define ASTR 132   // A pair stride (== 4 mod 32 -> conflict-free fragments)
#define WSTR 36    // W pair stride (== 4 mod 32)
#define PROJ_SMEM_BYTES ((2 * 64 * ASTR + 2 * 128 * WSTR) * 4)   // 104448

__global__ __launch_bounds__(256, 2)
void proj_mma_kernel(const float* __restrict__ wq,
                     const float* __restrict__ wk,
                     const float* __restrict__ cosb,
                     const float* __restrict__ sinb)
{
    extern __shared__ uint32_t sm[];
    uint32_t* sAh = sm;
    uint32_t* sAl = sm + 64 * ASTR;
    uint32_t* sWh = sm + 2 * 64 * ASTR;
    uint32_t* sWl = sm + 2 * 64 * ASTR + 128 * WSTR;

    const int bid0 = blockIdx.x;
    const bool isQ = bid0 < BB * HQ * 8;
    const int bid  = isQ ? bid0 : bid0 - BB * HQ * 8;
    const int NH   = isQ ? HQ : HK;
    const float* pool = isQ ? g_pq : g_pk;
    const float* w = isQ ? wq : wk;
    float* dst     = isQ ? g_qh : g_kh;

    const int mt8 = bid & 7;                 // NB/64 = 8 row tiles
    const int h   = (bid >> 3) % NH;
    const int b   = bid / (8 * NH);
    const int n0  = mt8 * 64;

    const int tid  = threadIdx.x;
    const int lane = tid & 31, wid = tid >> 5;
    const int wm = wid >> 2, wn = wid & 3;   // warp grid 2(m) x 4(n)
    const int g  = lane >> 2, tg = lane & 3;

    // ---- load pooled A tile [64 x 256] from gmem, split bf16 ----
    #pragma unroll
    for (int it = 0; it < 16; it++) {
        const int idx = tid + it * 256;
        const int n  = idx >> 6;             // 0..63
        const int f4 = idx & 63;             // float4 index 0..63
        float4 v = *(const float4*)&pool[(((size_t)(b * NH + h)) * NB + n0 + n) * 256 + f4 * 4];
        uint32_t hh, ll;
        split_pair(v.x, v.y, hh, ll);
        sAh[n * ASTR + f4 * 2]     = hh;  sAl[n * ASTR + f4 * 2]     = ll;
        split_pair(v.z, v.w, hh, ll);
        sAh[n * ASTR + f4 * 2 + 1] = hh;  sAl[n * ASTR + f4 * 2 + 1] = ll;
    }
    __syncthreads();

    float acc[2][4][4];
    #pragma unroll
    for (int i = 0; i < 2; i++)
        #pragma unroll
        for (int j = 0; j < 4; j++)
            #pragma unroll
            for (int r = 0; r < 4; r++) acc[i][j][r] = 0.f;

    for (int kc = 0; kc < 4; kc++) {         // 4 chunks of 64 cc
        // ---- load W chunk transposed from gmem, split bf16 ----
        #pragma unroll
        for (int it = 0; it < 16; it++) {
            const int idx = tid + it * 256;
            const int d  = idx & 127;
            const int cp = idx >> 7;         // 0..31 (cc pair within chunk)
            const int cc = kc * 64 + cp * 2;
            const float* wp2 = w + ((size_t)h * 256 + cc) * 128 + d;
            uint32_t hh, ll;
            split_pair(wp2[0], wp2[128], hh, ll);
            sWh[d * WSTR + cp] = hh;
            sWl[d * WSTR + cp] = ll;
        }
        __syncthreads();

        #pragma unroll
        for (int ksl = 0; ksl < 4; ksl++) {  // k16 steps within chunk
            const int ka = (kc * 4 + ksl) * 8;   // A pair offset (full K)
            const int kb = ksl * 8;              // W pair offset (chunk)
            uint32_t Ah[2][4], Al[2][4], Bh[4][2], Bl[4][2];

            #pragma unroll
            for (int mt = 0; mt < 2; mt++) {
                const uint32_t* ph = &sAh[(wm * 32 + mt * 16 + g) * ASTR + ka + tg];
                const uint32_t* pl = &sAl[(wm * 32 + mt * 16 + g) * ASTR + ka + tg];
                Ah[mt][0] = ph[0];  Ah[mt][1] = ph[8 * ASTR];
                Ah[mt][2] = ph[4];  Ah[mt][3] = ph[8 * ASTR + 4];
                Al[mt][0] = pl[0];  Al[mt][1] = pl[8 * ASTR];
                Al[mt][2] = pl[4];  Al[mt][3] = pl[8 * ASTR + 4];
            }
            #pragma unroll
            for (int nt = 0; nt < 4; nt++) {
                const uint32_t* ph = &sWh[(wn * 32 + nt * 8 + g) * WSTR + kb + tg];
                const uint32_t* pl = &sWl[(wn * 32 + nt * 8 + g) * WSTR + kb + tg];
                Bh[nt][0] = ph[0];  Bh[nt][1] = ph[4];
                Bl[nt][0] = pl[0];  Bl[nt][1] = pl[4];
            }

            #pragma unroll
            for (int mt = 0; mt < 2; mt++)
                #pragma unroll
                for (int nt = 0; nt < 4; nt++) {
                    mma_bf16(acc[mt][nt], Ah[mt], Bh[nt]);
                    mma_bf16(acc[mt][nt], Ah[mt], Bl[nt]);
                    mma_bf16(acc[mt][nt], Al[mt], Bh[nt]);
                }
        }
        __syncthreads();
    }

    // ---- epilogue: stage fp32 tile, RoPE, write ----
    float* stage = (float*)sm;               // 64 x ASTR floats (fits in sAh+sAl)
    #pragma unroll
    for (int mt = 0; mt < 2; mt++)
        #pragma unroll
        for (int nt = 0; nt < 4; nt++) {
            const int row = wm * 32 + mt * 16 + g;
            const int col = wn * 32 + nt * 8 + tg * 2;
            stage[row * ASTR + col]           = acc[mt][nt][0];
            stage[row * ASTR + col + 1]       = acc[mt][nt][1];
            stage[(row + 8) * ASTR + col]     = acc[mt][nt][2];
            stage[(row + 8) * ASTR + col + 1] = acc[mt][nt][3];
        }
    __syncthreads();

    #pragma unroll
    for (int it = 0; it < 16; it++) {
        const int idx = tid + it * 256;
        const int n  = idx >> 6;
        const int d  = (idx & 63) * 2;
        float2 v = *(const float2*)&stage[n * ASTR + d];
        float2 r;
        if (d < 64) {
            r.x = -stage[n * ASTR + d + 64];
            r.y = -stage[n * ASTR + d + 65];
        } else {
            r.x = stage[n * ASTR + d - 64];
            r.y = stage[n * ASTR + d - 63];
        }
        const size_t ci = ((size_t)b * NB + n0 + n) * HID + d;
        float2 c  = *(const float2*)&cosb[ci];
        float2 sn = *(const float2*)&sinb[ci];
        float2 o;
        o.x = v.x * c.x + r.x * sn.x;
        o.y = v.y * c.y + r.y * sn.y;
        *(float2*)&dst[(((size_t)(b * NH + h)) * NB + n0 + n) * HID + d] = o;
    }
}

// ---------------------------------------------------------------------------
// Kernel 2: block-causal logits via mma.sync bf16 split (unchanged).
// ---------------------------------------------------------------------------
#define LSTR 20

__global__ __launch_bounds__(256, 1)
void logits_mma_kernel(float* __restrict__ out)
{
    __shared__ uint32_t sAh[128 * LSTR], sAl[128 * LSTR];
    __shared__ uint32_t sBh[128 * LSTR], sBl[128 * LSTR];

    const int b  = blockIdx.z;
    const int h  = blockIdx.y;
    const int ti = blockIdx.x;
    const int mt4 = (ti >= 6) ? 3 : (ti >= 3) ? 2 : (ti >= 1) ? 1 : 0;
    const int jt  = ti - mt4 * (mt4 + 1) / 2;
    const int m0  = mt4 * 128;
    const int j0  = jt * 128;

    const float* Ag = g_qh + (((size_t)(b * HQ + h)) * NB + m0) * HID;
    const float* Bg = g_kh + (((size_t)(b * HK + h / (HQ / HK))) * NB + j0) * HID;

    const int tid  = threadIdx.x;
    const int lane = tid & 31, wid = tid >> 5;
    const int wm = wid >> 2, wn = wid & 3;
    const int g  = lane >> 2, tg = lane & 3;

    float acc[4][4][4];
    #pragma unroll
    for (int i = 0; i < 4; i++)
        #pragma unroll
        for (int j = 0; j < 4; j++)
            #pragma unroll
            for (int r = 0; r < 4; r++) acc[i][j][r] = 0.f;

    const int lr0 = tid >> 3;
    const int lq  = tid & 7;

    for (int kc = 0; kc < 4; kc++) {
        __syncthreads();
        #pragma unroll
        for (int pass = 0; pass < 4; pass++) {
            const int r = pass * 32 + lr0;
            float4 va = *(const float4*)&Ag[(size_t)r * HID + kc * 32 + lq * 4];
            uint32_t h0, l0, h1, l1;
            split_pair(va.x, va.y, h0, l0);
            split_pair(va.z, va.w, h1, l1);
            sAh[r * LSTR + lq * 2 + 0] = h0;  sAh[r * LSTR + lq * 2 + 1] = h1;
            sAl[r * LSTR + lq * 2 + 0] = l0;  sAl[r * LSTR + lq * 2 + 1] = l1;

            float4 vb = *(const float4*)&Bg[(size_t)r * HID + kc * 32 + lq * 4];
            split_pair(vb.x, vb.y, h0, l0);
            split_pair(vb.z, vb.w, h1, l1);
            sBh[r * LSTR + lq * 2 + 0] = h0;  sBh[r * LSTR + lq * 2 + 1] = h1;
            sBl[r * LSTR + lq * 2 + 0] = l0;  sBl[r * LSTR + lq * 2 + 1] = l1;
        }
        __syncthreads();

        #pragma unroll
        for (int ks = 0; ks < 2; ks++) {
            const int kb = ks * 8;
            uint32_t Ah[4][4], Al[4][4], Bh[4][2], Bl[4][2];

            #pragma unroll
            for (int mt = 0; mt < 4; mt++) {
                const int r = wm * 64 + mt * 16 + g;
                const uint32_t* ph = &sAh[r * LSTR + kb + tg];
                const uint32_t* pl = &sAl[r * LSTR + kb + tg];
                Ah[mt][0] = ph[0];  Ah[mt][1] = ph[8 * LSTR];
                Ah[mt][2] = ph[4];  Ah[mt][3] = ph[8 * LSTR + 4];
                Al[mt][0] = pl[0];  Al[mt][1] = pl[8 * LSTR];
                Al[mt][2] = pl[4];  Al[mt][3] = pl[8 * LSTR + 4];
            }
            #pragma unroll
            for (int nt = 0; nt < 4; nt++) {
                const int n = wn * 32 + nt * 8 + g;
                const uint32_t* ph = &sBh[n * LSTR + kb + tg];
                const uint32_t* pl = &sBl[n * LSTR + kb + tg];
                Bh[nt][0] = ph[0];  Bh[nt][1] = ph[4];
                Bl[nt][0] = pl[0];  Bl[nt][1] = pl[4];
            }

            #pragma unroll
            for (int mt = 0; mt < 4; mt++)
                #pragma unroll
                for (int nt = 0; nt < 4; nt++) {
                    mma_bf16(acc[mt][nt], Ah[mt], Bh[nt]);
                    mma_bf16(acc[mt][nt], Ah[mt], Bl[nt]);
                    mma_bf16(acc[mt][nt], Al[mt], Bh[nt]);
                }
        }
    }

    const float scale = 0.08838834764831845f;
    #pragma unroll
    for (int mt = 0; mt < 4; mt++) {
        #pragma unroll
        for (int nt = 0; nt < 4; nt++) {
            const int row = m0 + wm * 64 + mt * 16 + g;
            const int col = j0 + wn * 32 + nt * 8 + tg * 2;
            float* p0 = out + (((size_t)(b * HQ + h)) * NB + row) * NB + col;
            *(float2*)p0 = make_float2(acc[mt][nt][0] * scale, acc[mt][nt][1] * scale);
            *(float2*)(p0 + 8 * NB) = make_float2(acc[mt][nt][2] * scale, acc[mt][nt][3] * scale);
        }
    }
}

// ---------------------------------------------------------------------------
// Kernel 3: masked softmax, one WARP per row (unchanged).
// ---------------------------------------------------------------------------
__global__ __launch_bounds__(512)
void softmax_kernel(float* __restrict__ out)
{
    const int wid  = threadIdx.x >> 5;
    const int lane = threadIdx.x & 31;
    const int row  = blockIdx.x * 16 + wid;      // ((b*HQ+h)*NB + i)
    const int i    = row & (NB - 1);
    float* p = out + (size_t)row * NB;

    float4 v[4];
    float mx = -3.0e38f;
    #pragma unroll
    for (int w = 0; w < 4; w++) {
        const int j = w * 128 + lane * 4;
        if (j <= i) {
            v[w] = *(const float4*)&p[j];
            if (j + 1 > i) v[w].y = -3.0e38f;
            if (j + 2 > i) v[w].z = -3.0e38f;
            if (j + 3 > i) v[w].w = -3.0e38f;
        } else {
            v[w] = make_float4(-3.0e38f, -3.0e38f, -3.0e38f, -3.0e38f);
        }
        mx = fmaxf(mx, fmaxf(fmaxf(v[w].x, v[w].y), fmaxf(v[w].z, v[w].w)));
    }
    #pragma unroll
    for (int o = 16; o; o >>= 1) mx = fmaxf(mx, __shfl_xor_sync(0xffffffffu, mx, o));

    float s = 0.f;
    #pragma unroll
    for (int w = 0; w < 4; w++) {
        v[w].x = (v[w].x > -1.0e38f) ? expf(v[w].x - mx) : 0.f;
        v[w].y = (v[w].y > -1.0e38f) ? expf(v[w].y - mx) : 0.f;
        v[w].z = (v[w].z > -1.0e38f) ? expf(v[w].z - mx) : 0.f;
        v[w].w = (v[w].w > -1.0e38f) ? expf(v[w].w - mx) : 0.f;
        s += v[w].x + v[w].y + v[w].z + v[w].w;
    }
    #pragma unroll
    for (int o = 16; o; o >>= 1) s += __shfl_xor_sync(0xffffffffu, s, o);

    const float inv = 1.0f / s;
    #pragma unroll
    for (int w = 0; w < 4; w++) {
        float4 o4;
        o4.x = v[w].x * inv;  o4.y = v[w].y * inv;
        o4.z = v[w].z * inv;  o4.w = v[w].w * inv;
        *(float4*)&p[w * 128 + lane * 4] = o4;
    }
}

// ---------------------------------------------------------------------------
extern "C" void kernel_launch(void* const* d_in, const int* in_sizes, int n_in,
                              void* d_out, int out_size)
{
    const float* q    = (const float*)d_in[0];
    const float* k    = (const float*)d_in[1];
    const float* cosb = (const float*)d_in[3];
    const float* sinb = (const float*)d_in[4];
    const float* wq   = (const float*)d_in[5];
    const float* wk   = (const float*)d_in[6];
    float* out = (float*)d_out;

    cudaFuncSetAttribute(proj_mma_kernel,
                         cudaFuncAttributeMaxDynamicSharedMemorySize, PROJ_SMEM_BYTES);

    // 0) pooling at full occupancy (pure streaming)
    const int pool_threads = (BB * HQ * NB * 32 + BB * HK * NB * 32);
    pool_kernel<<<pool_threads / 256, 256>>>(q, k);

    // 1) projection (tensor) + rope — q and k merged into one grid
    proj_mma_kernel<<<BB * HQ * 8 + BB * HK * 8, 256, PROJ_SMEM_BYTES>>>(
        wq, wk, cosb, sinb);

    // 2) causal logits on tensor cores (bf16 split x3, mma.sync)
    dim3 lg(10, HQ, BB);
    logits_mma_kernel<<<lg, 256>>>(out);

    // 3) masked softmax in place (warp per row)
    softmax_kernel<<<BB * HQ * NB / 16, 512>>>(out);
}